// round 1
// baseline (speedup 1.0000x reference)
#include <cuda_runtime.h>
#include <math.h>

// Fused CNN + analytic quantum circuit.
// One CTA per image, 320 threads.
//
// Quantum part collapses analytically:
//   P_i(1) = (1 + sin f_i)/2
//   <Z_j>  = - sum_{b in {0,1}^4} prod_i P_i(b_i) * sin( sum_{i: b_i=1} w[i][j] )
//   out_j  = sigmoid(10 * <Z_j>)

__global__ __launch_bounds__(320, 4)
void hybrid_kernel(const float* __restrict__ x,
                   const float* __restrict__ w1g, const float* __restrict__ b1g,
                   const float* __restrict__ w2g, const float* __restrict__ b2g,
                   const float* __restrict__ dwg, const float* __restrict__ dbg,
                   const float* __restrict__ qwg,
                   float* __restrict__ out)
{
    // s_buf union: phase A = input image [784]; phase B = conv2 rows [10][10][32]
    __shared__ float s_buf[3200];
    __shared__ float s_w1[144];
    __shared__ float s_b1[16];
    __shared__ float s_p1[16][13][13];   // pooled conv1: [ci][y][x]
    __shared__ float s_w2[4608];         // [ky][kx][ci][co] (HWIO flattened)
    __shared__ float s_b2[32];
    __shared__ float s_p2[800];          // pooled conv2, flatten order [(r*5+c)*32+co]
    __shared__ float s_feat[4];

    const int tid = threadIdx.x;
    const int img = blockIdx.x;

    // ---------------- load phase ----------------
    const float* xin = x + img * 784;
    for (int i = tid; i < 784; i += 320) s_buf[i] = xin[i];
    for (int i = tid; i < 144; i += 320) s_w1[i] = w1g[i];
    if (tid < 16) s_b1[tid] = b1g[tid];
    for (int i = tid; i < 4608; i += 320) s_w2[i] = w2g[i];
    if (tid < 32) s_b2[tid] = b2g[tid];
    if (tid < 4)  s_feat[tid] = dbg[tid];
    __syncthreads();

    // ---------------- conv1 (3x3x1x16) + relu + 2x2 maxpool -> s_p1[16][13][13] ----
    // unit = (co in 0..15, pooled-row py in 0..12): 208 units
    if (tid < 208) {
        const int co = tid & 15;
        const int py = tid >> 4;
        float w[9];
        #pragma unroll
        for (int k = 0; k < 9; k++) w[k] = s_w1[k * 16 + co];
        const float bias = s_b1[co];
        #pragma unroll 1
        for (int px = 0; px < 13; px++) {
            float best = -1e30f;
            #pragma unroll
            for (int dy = 0; dy < 2; dy++) {
                #pragma unroll
                for (int dx = 0; dx < 2; dx++) {
                    float acc = bias;
                    #pragma unroll
                    for (int ky = 0; ky < 3; ky++) {
                        #pragma unroll
                        for (int kx = 0; kx < 3; kx++) {
                            acc += s_buf[(2 * py + dy + ky) * 28 + (2 * px + dx + kx)]
                                   * w[ky * 3 + kx];
                        }
                    }
                    best = fmaxf(best, acc);
                }
            }
            s_p1[co][py][px] = fmaxf(best, 0.0f);   // relu(max) == max(relu)
        }
    }
    __syncthreads();

    // ---------------- conv2 (3x3x16x32) + relu -> s_buf as [oy 0..9][ox 0..9][co] --
    // unit = (co in 0..31, conv-row oy in 0..9): exactly 320 units.
    // Only rows/cols 0..9 are needed by the VALID 2x2 pool over the 11x11 output.
    {
        const int co = tid & 31;
        const int oy = tid >> 5;               // 0..9
        const float bias = s_b2[co];
        float acc[10];
        #pragma unroll
        for (int i = 0; i < 10; i++) acc[i] = bias;

        #pragma unroll 1
        for (int ci = 0; ci < 16; ci++) {
            #pragma unroll
            for (int ky = 0; ky < 3; ky++) {
                const float* ar = &s_p1[ci][oy + ky][0];
                const float wv0 = s_w2[((ky * 3 + 0) * 16 + ci) * 32 + co];
                const float wv1 = s_w2[((ky * 3 + 1) * 16 + ci) * 32 + co];
                const float wv2 = s_w2[((ky * 3 + 2) * 16 + ci) * 32 + co];
                float a0 = ar[0], a1 = ar[1];
                #pragma unroll
                for (int ox = 0; ox < 10; ox++) {
                    const float a2 = ar[ox + 2];
                    acc[ox] += a0 * wv0;
                    acc[ox] += a1 * wv1;
                    acc[ox] += a2 * wv2;
                    a0 = a1; a1 = a2;
                }
            }
        }
        #pragma unroll
        for (int ox = 0; ox < 10; ox++)
            s_buf[(oy * 10 + ox) * 32 + co] = fmaxf(acc[ox], 0.0f);
    }
    __syncthreads();

    // ---------------- 2x2 maxpool -> s_p2[800] in NHWC flatten order --------------
    for (int o = tid; o < 800; o += 320) {
        const int co  = o & 31;
        const int pos = o >> 5;
        const int r   = pos / 5;
        const int cl  = pos - r * 5;
        const float v0 = s_buf[((2 * r    ) * 10 + 2 * cl    ) * 32 + co];
        const float v1 = s_buf[((2 * r    ) * 10 + 2 * cl + 1) * 32 + co];
        const float v2 = s_buf[((2 * r + 1) * 10 + 2 * cl    ) * 32 + co];
        const float v3 = s_buf[((2 * r + 1) * 10 + 2 * cl + 1) * 32 + co];
        s_p2[o] = fmaxf(fmaxf(v0, v1), fmaxf(v2, v3));
    }
    __syncthreads();

    // ---------------- dense 800 -> 4 (accumulate into s_feat, bias preloaded) -----
    {
        float p0 = 0.f, p1 = 0.f, p2 = 0.f, p3 = 0.f;
        for (int k = tid; k < 800; k += 320) {
            const float v = s_p2[k];
            const float4 w = *(const float4*)(dwg + k * 4);
            p0 += v * w.x; p1 += v * w.y; p2 += v * w.z; p3 += v * w.w;
        }
        #pragma unroll
        for (int off = 16; off; off >>= 1) {
            p0 += __shfl_down_sync(0xffffffffu, p0, off);
            p1 += __shfl_down_sync(0xffffffffu, p1, off);
            p2 += __shfl_down_sync(0xffffffffu, p2, off);
            p3 += __shfl_down_sync(0xffffffffu, p3, off);
        }
        if ((tid & 31) == 0) {
            atomicAdd(&s_feat[0], p0);
            atomicAdd(&s_feat[1], p1);
            atomicAdd(&s_feat[2], p2);
            atomicAdd(&s_feat[3], p3);
        }
    }
    __syncthreads();

    // ---------------- analytic quantum circuit + sigmoid ---------------------------
    if (tid < 4) {
        const int j = tid;
        float pr1[4];
        #pragma unroll
        for (int i = 0; i < 4; i++) {
            const float f = tanhf(s_feat[i]);
            pr1[i] = 0.5f * (1.0f + sinf(f));      // P(input qubit i = 1)
        }
        float wj[4];
        #pragma unroll
        for (int i = 0; i < 4; i++) wj[i] = qwg[i * 4 + j];

        float q = 0.0f;
        #pragma unroll
        for (int b = 0; b < 16; b++) {
            float prob = 1.0f, ang = 0.0f;
            #pragma unroll
            for (int i = 0; i < 4; i++) {
                if (b & (1 << i)) { prob *= pr1[i];         ang += wj[i]; }
                else              { prob *= 1.0f - pr1[i]; }
            }
            q -= prob * sinf(ang);                 // <Z_j> contribution
        }
        out[img * 4 + j] = 1.0f / (1.0f + expf(-10.0f * q));
    }
}

extern "C" void kernel_launch(void* const* d_in, const int* in_sizes, int n_in,
                              void* d_out, int out_size)
{
    const float* x   = (const float*)d_in[0];
    const float* w1  = (const float*)d_in[1];
    const float* b1  = (const float*)d_in[2];
    const float* w2  = (const float*)d_in[3];
    const float* b2  = (const float*)d_in[4];
    const float* dw  = (const float*)d_in[5];
    const float* db  = (const float*)d_in[6];
    const float* qw  = (const float*)d_in[7];
    float* out = (float*)d_out;

    const int B = in_sizes[0] / 784;   // NHWC 28*28*1
    hybrid_kernel<<<B, 320>>>(x, w1, b1, w2, b2, dw, db, qw, out);
}

// round 3
// speedup vs baseline: 1.3329x; 1.3329x over previous
#include <cuda_runtime.h>
#include <math.h>

// Fused CNN + analytic quantum circuit. One CTA per image, 320 threads.
//
// Quantum part collapses analytically:
//   P_i(1) = (1 + sin f_i)/2
//   <Z_j>  = - sum_{b in {0,1}^4} prod_i P_i(b_i) * sin( sum_{i: b_i=1} w[i][j] )
//   out_j  = sigmoid(10 * <Z_j>)

// shared-memory layout (floats), total 11844 floats = 47376 B (< 48KB static limit)
#define OFF_BUF   0        // [3200] phase A: image[784]; phase B: conv2 out [10][10][32]
#define OFF_P1    3200     // [16][12][12] pooled conv1 (row stride 12 = 48B, 16B-aligned)
#define OFF_W2    5504     // [512][12]  conv2 weights [ci*32+co][9 taps + 3 pad]
#define OFF_P2    5504     // alias over W2 (dead after conv2): [800] pooled conv2
#define OFF_W1    11648    // [144]
#define OFF_B1    11792    // [16]
#define OFF_B2    11808    // [32]
#define OFF_FEAT  11840    // [4]
#define SM_FLOATS 11844

__global__ __launch_bounds__(320, 4)
void hybrid_kernel(const float* __restrict__ x,
                   const float* __restrict__ w1g, const float* __restrict__ b1g,
                   const float* __restrict__ w2g, const float* __restrict__ b2g,
                   const float* __restrict__ dwg, const float* __restrict__ dbg,
                   const float* __restrict__ qwg,
                   float* __restrict__ out)
{
    __shared__ __align__(16) float sm[SM_FLOATS];
    float* s_buf  = sm + OFF_BUF;
    float* s_p1   = sm + OFF_P1;
    float* s_w2   = sm + OFF_W2;
    float* s_p2   = sm + OFF_P2;
    float* s_w1   = sm + OFF_W1;
    float* s_b1   = sm + OFF_B1;
    float* s_b2   = sm + OFF_B2;
    float* s_feat = sm + OFF_FEAT;

    const int tid = threadIdx.x;
    const int img = blockIdx.x;

    // ---------------- load phase ----------------
    const float* xin = x + img * 784;
    for (int i = tid; i < 784; i += 320) s_buf[i] = xin[i];
    for (int i = tid; i < 144; i += 320) s_w1[i] = w1g[i];
    if (tid < 16) s_b1[tid] = b1g[tid];
    // transpose conv2 weights HWIO [k][ci][co] -> [ci*32+co][12]
    for (int t = tid; t < 512; t += 320) {       // t = ci*32+co
        #pragma unroll
        for (int k = 0; k < 9; k++) s_w2[t * 12 + k] = w2g[k * 512 + t];
    }
    if (tid < 32) s_b2[tid] = b2g[tid];
    if (tid < 4)  s_feat[tid] = dbg[tid];
    __syncthreads();

    // ---------------- conv1 (3x3x1x16) + relu + 2x2 maxpool -> s_p1[16][12][12] ----
    // Only pooled rows/cols 0..11 are consumed downstream. 192 units, sliding window.
    if (tid < 192) {
        const int co = tid & 15;
        const int py = tid >> 4;               // 0..11
        float w[9];
        #pragma unroll
        for (int k = 0; k < 9; k++) w[k] = s_w1[k * 16 + co];
        const float bias = s_b1[co];
        const float* in0 = &s_buf[(2 * py) * 28];
        float* p1row = &s_p1[(co * 12 + py) * 12];

        float win[4][4];
        #pragma unroll
        for (int r = 0; r < 4; r++) {
            win[r][2] = in0[r * 28 + 0];
            win[r][3] = in0[r * 28 + 1];
        }
        #pragma unroll 1
        for (int px = 0; px < 12; px++) {
            #pragma unroll
            for (int r = 0; r < 4; r++) {
                win[r][0] = win[r][2];
                win[r][1] = win[r][3];
                win[r][2] = in0[r * 28 + 2 * px + 2];
                win[r][3] = in0[r * 28 + 2 * px + 3];
            }
            float best = -1e30f;
            #pragma unroll
            for (int dy = 0; dy < 2; dy++) {
                #pragma unroll
                for (int dx = 0; dx < 2; dx++) {
                    float acc = bias;
                    #pragma unroll
                    for (int ky = 0; ky < 3; ky++) {
                        #pragma unroll
                        for (int kx = 0; kx < 3; kx++)
                            acc += win[dy + ky][dx + kx] * w[ky * 3 + kx];
                    }
                    best = fmaxf(best, acc);
                }
            }
            p1row[px] = fmaxf(best, 0.0f);
        }
    }
    __syncthreads();

    // ---------------- conv2 (3x3x16x32) + relu -> s_buf [oy][ox][co] ---------------
    // unit = (co 0..31, row oy 0..9): exactly 320 units.
    {
        const int co = tid & 31;
        const int oy = tid >> 5;
        const float bias = s_b2[co];
        float acc[10];
        #pragma unroll
        for (int i = 0; i < 10; i++) acc[i] = bias;

        #pragma unroll 1
        for (int ci = 0; ci < 16; ci++) {
            // 9 weights via 3x LDS.128
            const float4* wp = (const float4*)&s_w2[(ci * 32 + co) * 12];
            const float4 wa = wp[0];
            const float4 wb = wp[1];
            const float4 wc = wp[2];
            const float wv[9] = {wa.x, wa.y, wa.z, wa.w, wb.x, wb.y, wb.z, wb.w, wc.x};

            #pragma unroll
            for (int ky = 0; ky < 3; ky++) {
                // 12-float activation row via 3 broadcast LDS.128
                const float4* rp = (const float4*)&s_p1[(ci * 12 + oy + ky) * 12];
                const float4 A = rp[0], B = rp[1], C = rp[2];
                const float a[12] = {A.x, A.y, A.z, A.w, B.x, B.y, B.z, B.w,
                                     C.x, C.y, C.z, C.w};
                const float w0 = wv[ky * 3 + 0];
                const float w1 = wv[ky * 3 + 1];
                const float w2 = wv[ky * 3 + 2];
                #pragma unroll
                for (int ox = 0; ox < 10; ox++) {
                    acc[ox] += a[ox] * w0;
                    acc[ox] += a[ox + 1] * w1;
                    acc[ox] += a[ox + 2] * w2;
                }
            }
        }
        #pragma unroll
        for (int ox = 0; ox < 10; ox++)
            s_buf[(oy * 10 + ox) * 32 + co] = fmaxf(acc[ox], 0.0f);
    }
    __syncthreads();   // also retires all s_w2 reads before s_p2 aliases it

    // ---------------- 2x2 maxpool -> s_p2[800] (NHWC flatten) ----------------------
    for (int o = tid; o < 800; o += 320) {
        const int co  = o & 31;
        const int pos = o >> 5;
        const int r   = pos / 5;
        const int cl  = pos - r * 5;
        const float v0 = s_buf[((2 * r    ) * 10 + 2 * cl    ) * 32 + co];
        const float v1 = s_buf[((2 * r    ) * 10 + 2 * cl + 1) * 32 + co];
        const float v2 = s_buf[((2 * r + 1) * 10 + 2 * cl    ) * 32 + co];
        const float v3 = s_buf[((2 * r + 1) * 10 + 2 * cl + 1) * 32 + co];
        s_p2[o] = fmaxf(fmaxf(v0, v1), fmaxf(v2, v3));
    }
    __syncthreads();

    // ---------------- dense 800 -> 4 ------------------------------------------------
    {
        float p0 = 0.f, p1 = 0.f, p2 = 0.f, p3 = 0.f;
        for (int k = tid; k < 800; k += 320) {
            const float v = s_p2[k];
            const float4 w = *(const float4*)(dwg + k * 4);
            p0 += v * w.x; p1 += v * w.y; p2 += v * w.z; p3 += v * w.w;
        }
        #pragma unroll
        for (int off = 16; off; off >>= 1) {
            p0 += __shfl_down_sync(0xffffffffu, p0, off);
            p1 += __shfl_down_sync(0xffffffffu, p1, off);
            p2 += __shfl_down_sync(0xffffffffu, p2, off);
            p3 += __shfl_down_sync(0xffffffffu, p3, off);
        }
        if ((tid & 31) == 0) {
            atomicAdd(&s_feat[0], p0);
            atomicAdd(&s_feat[1], p1);
            atomicAdd(&s_feat[2], p2);
            atomicAdd(&s_feat[3], p3);
        }
    }
    __syncthreads();

    // ---------------- analytic quantum circuit + sigmoid ---------------------------
    if (tid < 4) {
        const int j = tid;
        float pr1[4];
        #pragma unroll
        for (int i = 0; i < 4; i++) {
            const float f = tanhf(s_feat[i]);
            pr1[i] = 0.5f * (1.0f + sinf(f));
        }
        float wj[4];
        #pragma unroll
        for (int i = 0; i < 4; i++) wj[i] = qwg[i * 4 + j];

        float q = 0.0f;
        #pragma unroll
        for (int b = 0; b < 16; b++) {
            float prob = 1.0f, ang = 0.0f;
            #pragma unroll
            for (int i = 0; i < 4; i++) {
                if (b & (1 << i)) { prob *= pr1[i];        ang += wj[i]; }
                else              { prob *= 1.0f - pr1[i]; }
            }
            q -= prob * sinf(ang);
        }
        out[img * 4 + j] = 1.0f / (1.0f + expf(-10.0f * q));
    }
}

extern "C" void kernel_launch(void* const* d_in, const int* in_sizes, int n_in,
                              void* d_out, int out_size)
{
    const float* x   = (const float*)d_in[0];
    const float* w1  = (const float*)d_in[1];
    const float* b1  = (const float*)d_in[2];
    const float* w2  = (const float*)d_in[3];
    const float* b2  = (const float*)d_in[4];
    const float* dw  = (const float*)d_in[5];
    const float* db  = (const float*)d_in[6];
    const float* qw  = (const float*)d_in[7];
    float* out = (float*)d_out;

    const int B = in_sizes[0] / 784;   // NHWC 28*28*1
    hybrid_kernel<<<B, 320>>>(x, w1, b1, w2, b2, dw, db, qw, out);
}

// round 4
// speedup vs baseline: 1.3744x; 1.0311x over previous
#include <cuda_runtime.h>
#include <math.h>

// Fused CNN + analytic quantum circuit. One CTA per TWO images, 320 threads.
// Weights in smem are kept in native HWIO order (conflict-free coalesced LDS),
// and each weight load is amortized over 2 images' worth of FMAs.
//
// Quantum part collapses analytically:
//   P_i(1) = (1 + sin f_i)/2
//   <Z_j>  = - sum_{b in {0,1}^4} prod_i P_i(b_i) * sin( sum_{i: b_i=1} w[i][j] )
//   out_j  = sigmoid(10 * <Z_j>)

// dynamic shared-memory layout (floats)
#define OFF_OUT   0        // [6400] phase A: both images [2*784]; phase B: conv2 out [2][10*10*32]
#define OFF_P1    6400     // [2][16][12][12] pooled conv1 (row = 12 floats = 48B, 16B-aligned)
#define OFF_W2    11008    // [4608] conv2 weights, native HWIO [k][ci][co]
#define OFF_P2    11008    // alias over W2 (dead after conv2): [2][800]
#define OFF_W1    15616    // [144]
#define OFF_B1    15760    // [16]
#define OFF_B2    15776    // [32]
#define OFF_FEAT  15808    // [8]  (dense out + bias, 2 images x 4)
#define SM_FLOATS 15816
#define SM_BYTES  (SM_FLOATS * 4)

__global__ __launch_bounds__(320, 2)
void hybrid_kernel(const float* __restrict__ x,
                   const float* __restrict__ w1g, const float* __restrict__ b1g,
                   const float* __restrict__ w2g, const float* __restrict__ b2g,
                   const float* __restrict__ dwg, const float* __restrict__ dbg,
                   const float* __restrict__ qwg,
                   float* __restrict__ out, int B)
{
    extern __shared__ __align__(16) float sm[];
    float* s_out  = sm + OFF_OUT;
    float* s_p1   = sm + OFF_P1;
    float* s_w2   = sm + OFF_W2;
    float* s_p2   = sm + OFF_P2;
    float* s_w1   = sm + OFF_W1;
    float* s_b1   = sm + OFF_B1;
    float* s_b2   = sm + OFF_B2;
    float* s_feat = sm + OFF_FEAT;

    const int tid  = threadIdx.x;
    const int img0 = blockIdx.x * 2;
    const bool has2 = (img0 + 1) < B;
    const int nimg = has2 ? 2 : 1;

    // ---------------- load phase ----------------
    // two consecutive images are contiguous in x: one coalesced copy
    {
        const float* xin = x + img0 * 784;
        const int cnt = nimg * 784;
        for (int i = tid; i < cnt; i += 320) s_out[i] = xin[i];
    }
    // conv2 weights: straight coalesced float4 copy (4608 floats)
    {
        const float4* src = (const float4*)w2g;
        float4* dst = (float4*)s_w2;
        for (int i = tid; i < 1152; i += 320) dst[i] = src[i];
    }
    for (int i = tid; i < 144; i += 320) s_w1[i] = w1g[i];
    if (tid < 16) s_b1[tid] = b1g[tid];
    if (tid < 32) s_b2[tid] = b2g[tid];
    if (tid < 8)  s_feat[tid] = dbg[tid & 3];
    __syncthreads();

    // ---------------- conv1 (3x3x1x16) + relu + 2x2 maxpool -> s_p1[2][16][12][12] --
    // Only pooled rows/cols 0..11 feed conv2's useful region. 192 units, loop images.
    if (tid < 192) {
        const int co = tid & 15;
        const int py = tid >> 4;               // 0..11
        float w[9];
        #pragma unroll
        for (int k = 0; k < 9; k++) w[k] = s_w1[k * 16 + co];
        const float bias = s_b1[co];

        #pragma unroll 1
        for (int im = 0; im < 2; im++) {
            const float* in0 = s_out + im * 784 + (2 * py) * 28;
            float* p1row = s_p1 + im * 2304 + (co * 12 + py) * 12;

            float win[4][4];
            #pragma unroll
            for (int r = 0; r < 4; r++) {
                win[r][2] = in0[r * 28 + 0];
                win[r][3] = in0[r * 28 + 1];
            }
            #pragma unroll 1
            for (int px = 0; px < 12; px++) {
                #pragma unroll
                for (int r = 0; r < 4; r++) {
                    win[r][0] = win[r][2];
                    win[r][1] = win[r][3];
                    win[r][2] = in0[r * 28 + 2 * px + 2];
                    win[r][3] = in0[r * 28 + 2 * px + 3];
                }
                float best = -1e30f;
                #pragma unroll
                for (int dy = 0; dy < 2; dy++) {
                    #pragma unroll
                    for (int dx = 0; dx < 2; dx++) {
                        float acc = bias;
                        #pragma unroll
                        for (int ky = 0; ky < 3; ky++) {
                            #pragma unroll
                            for (int kx = 0; kx < 3; kx++)
                                acc += win[dy + ky][dx + kx] * w[ky * 3 + kx];
                        }
                        best = fmaxf(best, acc);
                    }
                }
                p1row[px] = fmaxf(best, 0.0f);
            }
        }
    }
    __syncthreads();

    // ---------------- conv2 (3x3x16x32) + relu, 2 images -> s_out [im][oy][ox][co] --
    // unit = (co 0..31, row oy 0..9): 320 units; each does 2 images (20 accumulators).
    {
        const int co = tid & 31;
        const int oy = tid >> 5;
        const float bias = s_b2[co];
        float accA[10], accB[10];
        #pragma unroll
        for (int i = 0; i < 10; i++) { accA[i] = bias; accB[i] = bias; }

        #pragma unroll 1
        for (int ci = 0; ci < 16; ci++) {
            #pragma unroll
            for (int ky = 0; ky < 3; ky++) {
                // weights: lanes = co -> consecutive addresses, conflict-free (1 wf each)
                const float* wrow = s_w2 + (ky * 3) * 512 + ci * 32 + co;
                const float w0 = wrow[0];
                const float w1 = wrow[512];
                const float w2 = wrow[1024];
                const int rbase = (ci * 12 + oy + ky) * 12;

                {   // image A: 12-float row via 3 broadcast LDS.128
                    const float4* rp = (const float4*)(s_p1 + rbase);
                    const float4 A = rp[0], Bv = rp[1], C = rp[2];
                    const float a[12] = {A.x, A.y, A.z, A.w, Bv.x, Bv.y, Bv.z, Bv.w,
                                         C.x, C.y, C.z, C.w};
                    #pragma unroll
                    for (int ox = 0; ox < 10; ox++) {
                        accA[ox] += a[ox] * w0;
                        accA[ox] += a[ox + 1] * w1;
                        accA[ox] += a[ox + 2] * w2;
                    }
                }
                {   // image B
                    const float4* rp = (const float4*)(s_p1 + 2304 + rbase);
                    const float4 A = rp[0], Bv = rp[1], C = rp[2];
                    const float a[12] = {A.x, A.y, A.z, A.w, Bv.x, Bv.y, Bv.z, Bv.w,
                                         C.x, C.y, C.z, C.w};
                    #pragma unroll
                    for (int ox = 0; ox < 10; ox++) {
                        accB[ox] += a[ox] * w0;
                        accB[ox] += a[ox + 1] * w1;
                        accB[ox] += a[ox + 2] * w2;
                    }
                }
            }
        }
        #pragma unroll
        for (int ox = 0; ox < 10; ox++) {
            s_out[(oy * 10 + ox) * 32 + co]        = fmaxf(accA[ox], 0.0f);
            s_out[3200 + (oy * 10 + ox) * 32 + co] = fmaxf(accB[ox], 0.0f);
        }
    }
    __syncthreads();   // also retires all s_w2 reads before s_p2 aliases it

    // ---------------- 2x2 maxpool -> s_p2[2][800] (NHWC flatten) -------------------
    for (int o = tid; o < 1600; o += 320) {
        const int im  = o >> 9 >= 1 ? (o >= 800) : (o >= 800);  // o/800
        const int oo  = o - (o >= 800 ? 800 : 0);
        const int co  = oo & 31;
        const int pos = oo >> 5;
        const int r   = pos / 5;
        const int cl  = pos - r * 5;
        const float* base = s_out + (o >= 800 ? 3200 : 0);
        const float v0 = base[((2 * r    ) * 10 + 2 * cl    ) * 32 + co];
        const float v1 = base[((2 * r    ) * 10 + 2 * cl + 1) * 32 + co];
        const float v2 = base[((2 * r + 1) * 10 + 2 * cl    ) * 32 + co];
        const float v3 = base[((2 * r + 1) * 10 + 2 * cl + 1) * 32 + co];
        s_p2[o] = fmaxf(fmaxf(v0, v1), fmaxf(v2, v3));
        (void)im;
    }
    __syncthreads();

    // ---------------- dense 800 -> 4, both images (one weight load serves both) ----
    {
        float pA0 = 0.f, pA1 = 0.f, pA2 = 0.f, pA3 = 0.f;
        float pB0 = 0.f, pB1 = 0.f, pB2 = 0.f, pB3 = 0.f;
        for (int k = tid; k < 800; k += 320) {
            const float vA = s_p2[k];
            const float vB = s_p2[800 + k];
            const float4 w = *(const float4*)(dwg + k * 4);
            pA0 += vA * w.x; pA1 += vA * w.y; pA2 += vA * w.z; pA3 += vA * w.w;
            pB0 += vB * w.x; pB1 += vB * w.y; pB2 += vB * w.z; pB3 += vB * w.w;
        }
        #pragma unroll
        for (int off = 16; off; off >>= 1) {
            pA0 += __shfl_down_sync(0xffffffffu, pA0, off);
            pA1 += __shfl_down_sync(0xffffffffu, pA1, off);
            pA2 += __shfl_down_sync(0xffffffffu, pA2, off);
            pA3 += __shfl_down_sync(0xffffffffu, pA3, off);
            pB0 += __shfl_down_sync(0xffffffffu, pB0, off);
            pB1 += __shfl_down_sync(0xffffffffu, pB1, off);
            pB2 += __shfl_down_sync(0xffffffffu, pB2, off);
            pB3 += __shfl_down_sync(0xffffffffu, pB3, off);
        }
        if ((tid & 31) == 0) {
            atomicAdd(&s_feat[0], pA0);
            atomicAdd(&s_feat[1], pA1);
            atomicAdd(&s_feat[2], pA2);
            atomicAdd(&s_feat[3], pA3);
            atomicAdd(&s_feat[4], pB0);
            atomicAdd(&s_feat[5], pB1);
            atomicAdd(&s_feat[6], pB2);
            atomicAdd(&s_feat[7], pB3);
        }
    }
    __syncthreads();

    // ---------------- analytic quantum circuit + sigmoid ---------------------------
    if (tid < 8) {
        const int im = tid >> 2;
        const int j  = tid & 3;
        if (im == 0 || has2) {
            float pr1[4];
            #pragma unroll
            for (int i = 0; i < 4; i++) {
                const float f = tanhf(s_feat[im * 4 + i]);
                pr1[i] = 0.5f * (1.0f + sinf(f));
            }
            float wj[4];
            #pragma unroll
            for (int i = 0; i < 4; i++) wj[i] = qwg[i * 4 + j];

            float q = 0.0f;
            #pragma unroll
            for (int b = 0; b < 16; b++) {
                float prob = 1.0f, ang = 0.0f;
                #pragma unroll
                for (int i = 0; i < 4; i++) {
                    if (b & (1 << i)) { prob *= pr1[i];        ang += wj[i]; }
                    else              { prob *= 1.0f - pr1[i]; }
                }
                q -= prob * sinf(ang);
            }
            out[(img0 + im) * 4 + j] = 1.0f / (1.0f + expf(-10.0f * q));
        }
    }
}

extern "C" void kernel_launch(void* const* d_in, const int* in_sizes, int n_in,
                              void* d_out, int out_size)
{
    const float* x   = (const float*)d_in[0];
    const float* w1  = (const float*)d_in[1];
    const float* b1  = (const float*)d_in[2];
    const float* w2  = (const float*)d_in[3];
    const float* b2  = (const float*)d_in[4];
    const float* dw  = (const float*)d_in[5];
    const float* db  = (const float*)d_in[6];
    const float* qw  = (const float*)d_in[7];
    float* out = (float*)d_out;

    const int B = in_sizes[0] / 784;   // NHWC 28*28*1
    static bool attr_set = false;
    if (!attr_set) {
        cudaFuncSetAttribute(hybrid_kernel,
                             cudaFuncAttributeMaxDynamicSharedMemorySize, SM_BYTES);
        attr_set = true;
    }
    hybrid_kernel<<<(B + 1) / 2, 320, SM_BYTES>>>(x, w1, b1, w2, b2, dw, db, qw, out, B);
}